// round 2
// baseline (speedup 1.0000x reference)
#include <cuda_runtime.h>

#define N_NODES 50000
#define N_EDGES 800000
#define DIM 128
#define HEADS 4
#define NEG_SLOPE 0.2f
#define LN_EPS 1e-5f

// Scratch (device globals: no allocation allowed in kernel_launch)
__device__ __align__(16) float g_xl[N_NODES * DIM];      // 25.6 MB
__device__ __align__(16) float g_xr[N_NODES * DIM];      // 25.6 MB
__device__ __align__(16) float g_e[N_EDGES * HEADS];     // 12.8 MB (logits, then exp in-place)
__device__ __align__(16) float g_m[N_NODES * HEADS];     // segment max
__device__ __align__(16) float g_den[N_NODES * HEADS];   // segment sum of exp
__device__ __align__(16) float g_acc[N_NODES * DIM];     // output accumulator
__device__ int g_src[N_EDGES];
__device__ int g_dst[N_EDGES];

__device__ __forceinline__ void atomicMaxFloat(float* addr, float val) {
    if (val >= 0.0f) {
        atomicMax((int*)addr, __float_as_int(val));
    } else {
        atomicMin((unsigned int*)addr, __float_as_uint(val));
    }
}

__device__ __forceinline__ void redAdd4(float* addr, float4 v) {
    asm volatile("red.global.add.v4.f32 [%0], {%1, %2, %3, %4};"
                 :: "l"(addr), "f"(v.x), "f"(v.y), "f"(v.z), "f"(v.w)
                 : "memory");
}

// ---------------------------------------------------------------------------
// Pass 0a: convert edge_index to int32, sniffing dtype at runtime.
// int64 data read as int64: all values in [0, N_NODES).
// int32 data read as int64: pairs combine to lo + hi*2^32, out of range
// with overwhelming probability over 16 samples.
// ---------------------------------------------------------------------------
__global__ void convert_idx_kernel(const void* __restrict__ ei_raw) {
    const long long* e64 = (const long long*)ei_raw;
    const int*       e32 = (const int*)ei_raw;
    bool is64 = true;
    #pragma unroll
    for (int j = 0; j < 16; j++) {
        long long v = e64[j];
        if (v < 0 || v >= N_NODES) is64 = false;
    }
    int i = blockIdx.x * blockDim.x + threadIdx.x;
    int stride = gridDim.x * blockDim.x;
    if (is64) {
        for (int e = i; e < N_EDGES; e += stride) {
            g_src[e] = (int)e64[e];
            g_dst[e] = (int)e64[N_EDGES + e];
        }
    } else {
        for (int e = i; e < N_EDGES; e += stride) {
            g_src[e] = e32[e];
            g_dst[e] = e32[N_EDGES + e];
        }
    }
}

// ---------------------------------------------------------------------------
// Pass 0b: init scratch
// ---------------------------------------------------------------------------
__global__ void init_kernel() {
    int i = blockIdx.x * blockDim.x + threadIdx.x;
    int stride = gridDim.x * blockDim.x;
    const float NEG_INF = __int_as_float(0xff800000);
    for (int j = i; j < N_NODES * DIM; j += stride) g_acc[j] = 0.0f;
    for (int j = i; j < N_NODES * HEADS; j += stride) {
        g_m[j] = NEG_INF;
        g_den[j] = 0.0f;
    }
}

// ---------------------------------------------------------------------------
// Pass 1: xl = x@W_l + b_l ; xr = x@W_r + b_r
// One warp computes 8 nodes (register-blocked so W row loads amortize 8x).
// Lane L owns output columns [4L, 4L+4).
// ---------------------------------------------------------------------------
__global__ void gemm_kernel(const float* __restrict__ x,
                            const float* __restrict__ Wl, const float* __restrict__ bl,
                            const float* __restrict__ Wr, const float* __restrict__ br) {
    const int lane = threadIdx.x & 31;
    const int warp = (blockIdx.x * blockDim.x + threadIdx.x) >> 5;
    const int nwarp = (gridDim.x * blockDim.x) >> 5;
    const int NPW = 8;

    float4 bl4 = ((const float4*)bl)[lane];
    float4 br4 = ((const float4*)br)[lane];

    for (int base = warp * NPW; base < N_NODES; base += nwarp * NPW) {
        float4 xv[NPW];
        #pragma unroll
        for (int i = 0; i < NPW; i++) {
            int n = base + i;
            xv[i] = (n < N_NODES) ? ((const float4*)(x + (size_t)n * DIM))[lane]
                                  : make_float4(0.f, 0.f, 0.f, 0.f);
        }
        float4 al[NPW], ar[NPW];
        #pragma unroll
        for (int i = 0; i < NPW; i++) {
            al[i] = make_float4(0.f, 0.f, 0.f, 0.f);
            ar[i] = make_float4(0.f, 0.f, 0.f, 0.f);
        }

        #pragma unroll
        for (int k4 = 0; k4 < DIM / 4; k4++) {
            #pragma unroll
            for (int c = 0; c < 4; c++) {
                const int k = k4 * 4 + c;
                float4 wl = ((const float4*)(Wl + (size_t)k * DIM))[lane];
                float4 wr = ((const float4*)(Wr + (size_t)k * DIM))[lane];
                #pragma unroll
                for (int i = 0; i < NPW; i++) {
                    float comp = (c == 0) ? xv[i].x : (c == 1) ? xv[i].y
                               : (c == 2) ? xv[i].z : xv[i].w;
                    float xk = __shfl_sync(0xffffffffu, comp, k4);
                    al[i].x += xk * wl.x; al[i].y += xk * wl.y;
                    al[i].z += xk * wl.z; al[i].w += xk * wl.w;
                    ar[i].x += xk * wr.x; ar[i].y += xk * wr.y;
                    ar[i].z += xk * wr.z; ar[i].w += xk * wr.w;
                }
            }
        }

        #pragma unroll
        for (int i = 0; i < NPW; i++) {
            int n = base + i;
            if (n < N_NODES) {
                float4 ol = make_float4(al[i].x + bl4.x, al[i].y + bl4.y,
                                        al[i].z + bl4.z, al[i].w + bl4.w);
                float4 orr = make_float4(ar[i].x + br4.x, ar[i].y + br4.y,
                                         ar[i].z + br4.z, ar[i].w + br4.w);
                ((float4*)(g_xl + (size_t)n * DIM))[lane] = ol;
                ((float4*)(g_xr + (size_t)n * DIM))[lane] = orr;
            }
        }
    }
}

// ---------------------------------------------------------------------------
// Pass 2: per-edge logits e[E,H] = att . leaky_relu(xl[src] + xr[dst])
//         + segment max into g_m. One warp per edge; 8 lanes per head.
// ---------------------------------------------------------------------------
__global__ void edge_logits_kernel(const float* __restrict__ att) {
    const int lane = threadIdx.x & 31;
    const int warp = (blockIdx.x * blockDim.x + threadIdx.x) >> 5;
    const int nwarp = (gridDim.x * blockDim.x) >> 5;

    float4 at = ((const float4*)att)[lane];  // att flattened [H*HD] matches feature layout

    for (int e = warp; e < N_EDGES; e += nwarp) {
        int s = g_src[e];
        int d = g_dst[e];
        float4 a = ((const float4*)(g_xl + (size_t)s * DIM))[lane];
        float4 b = ((const float4*)(g_xr + (size_t)d * DIM))[lane];
        float vx = a.x + b.x; vx = vx > 0.f ? vx : NEG_SLOPE * vx;
        float vy = a.y + b.y; vy = vy > 0.f ? vy : NEG_SLOPE * vy;
        float vz = a.z + b.z; vz = vz > 0.f ? vz : NEG_SLOPE * vz;
        float vw = a.w + b.w; vw = vw > 0.f ? vw : NEG_SLOPE * vw;
        float p = vx * at.x + vy * at.y + vz * at.z + vw * at.w;
        // reduce within each 8-lane head group
        p += __shfl_down_sync(0xffffffffu, p, 4);
        p += __shfl_down_sync(0xffffffffu, p, 2);
        p += __shfl_down_sync(0xffffffffu, p, 1);
        if ((lane & 7) == 0) {
            int h = lane >> 3;
            g_e[(size_t)e * HEADS + h] = p;
            atomicMaxFloat(&g_m[d * HEADS + h], p);
        }
    }
}

// ---------------------------------------------------------------------------
// Pass 3: ex = exp(e - m[dst]) in place; denom segment-sum (v4 red).
// One thread per edge.
// ---------------------------------------------------------------------------
__global__ void edge_exp_kernel() {
    int i = blockIdx.x * blockDim.x + threadIdx.x;
    int stride = gridDim.x * blockDim.x;
    for (int e = i; e < N_EDGES; e += stride) {
        int d = g_dst[e];
        float4 ev = ((const float4*)g_e)[e];
        float4 mv = ((const float4*)g_m)[d];
        float4 ex;
        ex.x = __expf(ev.x - mv.x);
        ex.y = __expf(ev.y - mv.y);
        ex.z = __expf(ev.z - mv.z);
        ex.w = __expf(ev.w - mv.w);
        ((float4*)g_e)[e] = ex;
        redAdd4(&g_den[d * HEADS], ex);
    }
}

// ---------------------------------------------------------------------------
// Pass 4: out[dst] += alpha * xl[src], alpha = ex / (denom[dst] + 1e-16).
// One warp per edge; vector red (1 v4 red per lane per edge).
// ---------------------------------------------------------------------------
__global__ void edge_scatter_kernel() {
    const int lane = threadIdx.x & 31;
    const int warp = (blockIdx.x * blockDim.x + threadIdx.x) >> 5;
    const int nwarp = (gridDim.x * blockDim.x) >> 5;

    for (int e = warp; e < N_EDGES; e += nwarp) {
        int s = g_src[e];
        int d = g_dst[e];
        float4 ex = ((const float4*)g_e)[e];
        float4 dn = ((const float4*)g_den)[d];
        int h = lane >> 3;
        float alpha = (h == 0) ? ex.x / (dn.x + 1e-16f)
                    : (h == 1) ? ex.y / (dn.y + 1e-16f)
                    : (h == 2) ? ex.z / (dn.z + 1e-16f)
                    :            ex.w / (dn.w + 1e-16f);
        float4 xs = ((const float4*)(g_xl + (size_t)s * DIM))[lane];
        float4 v = make_float4(xs.x * alpha, xs.y * alpha, xs.z * alpha, xs.w * alpha);
        redAdd4(g_acc + (size_t)d * DIM + lane * 4, v);
    }
}

// ---------------------------------------------------------------------------
// Pass 5: out = LN(acc + bias + x) * gamma + beta. One warp per node.
// ---------------------------------------------------------------------------
__global__ void ln_kernel(const float* __restrict__ x, const float* __restrict__ bias,
                          const float* __restrict__ gamma, const float* __restrict__ beta,
                          float* __restrict__ out) {
    const int lane = threadIdx.x & 31;
    const int warp = (blockIdx.x * blockDim.x + threadIdx.x) >> 5;
    const int nwarp = (gridDim.x * blockDim.x) >> 5;

    float4 bi = ((const float4*)bias)[lane];
    float4 g  = ((const float4*)gamma)[lane];
    float4 be = ((const float4*)beta)[lane];

    for (int n = warp; n < N_NODES; n += nwarp) {
        float4 a = ((const float4*)(g_acc + (size_t)n * DIM))[lane];
        float4 xv = ((const float4*)(x + (size_t)n * DIM))[lane];
        a.x += xv.x + bi.x;
        a.y += xv.y + bi.y;
        a.z += xv.z + bi.z;
        a.w += xv.w + bi.w;

        float s = a.x + a.y + a.z + a.w;
        #pragma unroll
        for (int off = 16; off > 0; off >>= 1)
            s += __shfl_xor_sync(0xffffffffu, s, off);
        float mu = s * (1.0f / DIM);

        float dx = a.x - mu, dy = a.y - mu, dz = a.z - mu, dw = a.w - mu;
        float q = dx * dx + dy * dy + dz * dz + dw * dw;
        #pragma unroll
        for (int off = 16; off > 0; off >>= 1)
            q += __shfl_xor_sync(0xffffffffu, q, off);
        float rs = rsqrtf(q * (1.0f / DIM) + LN_EPS);

        float4 o;
        o.x = dx * rs * g.x + be.x;
        o.y = dy * rs * g.y + be.y;
        o.z = dz * rs * g.z + be.z;
        o.w = dw * rs * g.w + be.w;
        ((float4*)(out + (size_t)n * DIM))[lane] = o;
    }
}

extern "C" void kernel_launch(void* const* d_in, const int* in_sizes, int n_in,
                              void* d_out, int out_size) {
    const float* x     = (const float*)d_in[0];
    const void*  ei    = d_in[1];
    const float* Wl    = (const float*)d_in[2];
    const float* bl    = (const float*)d_in[3];
    const float* Wr    = (const float*)d_in[4];
    const float* br    = (const float*)d_in[5];
    const float* att   = (const float*)d_in[6];
    const float* bias  = (const float*)d_in[7];
    const float* gamma = (const float*)d_in[8];
    const float* beta  = (const float*)d_in[9];
    float*       out   = (float*)d_out;

    convert_idx_kernel<<<1024, 256>>>(ei);
    init_kernel<<<1024, 256>>>();

    // 50000 nodes / 8 nodes-per-warp = 6250 warps; 8 warps/block -> 782 blocks
    gemm_kernel<<<782, 256>>>(x, Wl, bl, Wr, br);

    // warp-per-edge, grid-stride
    edge_logits_kernel<<<6144, 256>>>(att);

    // thread-per-edge: 800k threads
    edge_exp_kernel<<<3125, 256>>>();

    edge_scatter_kernel<<<6144, 256>>>();

    // warp-per-node: 6250 blocks of 8 warps
    ln_kernel<<<782, 256>>>(x, bias, gamma, beta, out);
}

// round 3
// speedup vs baseline: 1.0591x; 1.0591x over previous
#include <cuda_runtime.h>

#define N_NODES 50000
#define N_EDGES 800000
#define DIM 128
#define HEADS 4
#define NEG_SLOPE 0.2f
#define LN_EPS 1e-5f

#define SCAN_BLK 256
#define N_SCAN_BLKS ((N_NODES + SCAN_BLK - 1) / SCAN_BLK)   // 196

// Scratch (device globals: no allocation allowed in kernel_launch)
__device__ __align__(16) float g_xl[N_NODES * DIM];   // 25.6 MB
__device__ __align__(16) float g_xr[N_NODES * DIM];   // 25.6 MB
__device__ int g_deg[N_NODES];
__device__ int g_off[N_NODES];
__device__ int g_cursor[N_NODES];
__device__ int g_bsum[SCAN_BLK];                       // block sums for scan (196 used)
__device__ int g_csr_src[N_EDGES];
__device__ int g_is64;

// ---------------------------------------------------------------------------
// dtype sniff: int32 data viewed as int64 combines index pairs into >= 2^32
// values (out of [0, N_NODES)) with overwhelming probability over 16 samples.
// ---------------------------------------------------------------------------
__global__ void sniff_kernel(const void* __restrict__ ei_raw) {
    const long long* e64 = (const long long*)ei_raw;
    int ok = 1;
    for (int j = 0; j < 16; j++) {
        long long v = e64[j];
        if (v < 0 || v >= N_NODES) ok = 0;
    }
    g_is64 = ok;
}

__device__ __forceinline__ int load_idx(const void* raw, int pos, int is64) {
    return is64 ? (int)((const long long*)raw)[pos] : ((const int*)raw)[pos];
}

__global__ void zero_deg_kernel() {
    int i = blockIdx.x * blockDim.x + threadIdx.x;
    if (i < N_NODES) g_deg[i] = 0;
}

__global__ void hist_kernel(const void* __restrict__ ei_raw) {
    int is64 = g_is64;
    int i = blockIdx.x * blockDim.x + threadIdx.x;
    int stride = gridDim.x * blockDim.x;
    for (int e = i; e < N_EDGES; e += stride) {
        int d = load_idx(ei_raw, N_EDGES + e, is64);
        atomicAdd(&g_deg[d], 1);
    }
}

// scan pass 1: per-block inclusive scan of deg chunk; block total to g_bsum
__global__ void scan1_kernel() {
    __shared__ int sh[SCAN_BLK];
    int tid = threadIdx.x;
    int i = blockIdx.x * SCAN_BLK + tid;
    int v = (i < N_NODES) ? g_deg[i] : 0;
    sh[tid] = v;
    __syncthreads();
    #pragma unroll
    for (int o = 1; o < SCAN_BLK; o <<= 1) {
        int t = (tid >= o) ? sh[tid - o] : 0;
        __syncthreads();
        sh[tid] += t;
        __syncthreads();
    }
    if (i < N_NODES) g_off[i] = sh[tid];           // inclusive local
    if (tid == SCAN_BLK - 1) g_bsum[blockIdx.x] = sh[tid];
}

// scan pass 2: exclusive scan of block sums (single block)
__global__ void scan2_kernel() {
    __shared__ int sh[SCAN_BLK];
    int tid = threadIdx.x;
    int v = (tid < N_SCAN_BLKS) ? g_bsum[tid] : 0;
    sh[tid] = v;
    __syncthreads();
    #pragma unroll
    for (int o = 1; o < SCAN_BLK; o <<= 1) {
        int t = (tid >= o) ? sh[tid - o] : 0;
        __syncthreads();
        sh[tid] += t;
        __syncthreads();
    }
    g_bsum[tid] = sh[tid] - v;                     // exclusive
}

// scan pass 3: global exclusive offsets + cursor copy
__global__ void scan3_kernel() {
    int i = blockIdx.x * blockDim.x + threadIdx.x;
    if (i < N_NODES) {
        int excl = g_off[i] - g_deg[i] + g_bsum[blockIdx.x];
        g_off[i] = excl;
        g_cursor[i] = excl;
    }
}

__global__ void fill_kernel(const void* __restrict__ ei_raw) {
    int is64 = g_is64;
    int i = blockIdx.x * blockDim.x + threadIdx.x;
    int stride = gridDim.x * blockDim.x;
    for (int e = i; e < N_EDGES; e += stride) {
        int s = load_idx(ei_raw, e, is64);
        int d = load_idx(ei_raw, N_EDGES + e, is64);
        int pos = atomicAdd(&g_cursor[d], 1);
        g_csr_src[pos] = s;
    }
}

// ---------------------------------------------------------------------------
// GEMM: xl = x@W_l + b_l ; xr = x@W_r + b_r. Warp computes 8 nodes.
// ---------------------------------------------------------------------------
__global__ void gemm_kernel(const float* __restrict__ x,
                            const float* __restrict__ Wl, const float* __restrict__ bl,
                            const float* __restrict__ Wr, const float* __restrict__ br) {
    const int lane = threadIdx.x & 31;
    const int warp = (blockIdx.x * blockDim.x + threadIdx.x) >> 5;
    const int nwarp = (gridDim.x * blockDim.x) >> 5;
    const int NPW = 8;

    float4 bl4 = ((const float4*)bl)[lane];
    float4 br4 = ((const float4*)br)[lane];

    for (int base = warp * NPW; base < N_NODES; base += nwarp * NPW) {
        float4 xv[NPW];
        #pragma unroll
        for (int i = 0; i < NPW; i++) {
            int n = base + i;
            xv[i] = (n < N_NODES) ? ((const float4*)(x + (size_t)n * DIM))[lane]
                                  : make_float4(0.f, 0.f, 0.f, 0.f);
        }
        float4 al[NPW], ar[NPW];
        #pragma unroll
        for (int i = 0; i < NPW; i++) {
            al[i] = make_float4(0.f, 0.f, 0.f, 0.f);
            ar[i] = make_float4(0.f, 0.f, 0.f, 0.f);
        }

        #pragma unroll
        for (int k4 = 0; k4 < DIM / 4; k4++) {
            #pragma unroll
            for (int c = 0; c < 4; c++) {
                const int k = k4 * 4 + c;
                float4 wl = ((const float4*)(Wl + (size_t)k * DIM))[lane];
                float4 wr = ((const float4*)(Wr + (size_t)k * DIM))[lane];
                #pragma unroll
                for (int i = 0; i < NPW; i++) {
                    float comp = (c == 0) ? xv[i].x : (c == 1) ? xv[i].y
                               : (c == 2) ? xv[i].z : xv[i].w;
                    float xk = __shfl_sync(0xffffffffu, comp, k4);
                    al[i].x += xk * wl.x; al[i].y += xk * wl.y;
                    al[i].z += xk * wl.z; al[i].w += xk * wl.w;
                    ar[i].x += xk * wr.x; ar[i].y += xk * wr.y;
                    ar[i].z += xk * wr.z; ar[i].w += xk * wr.w;
                }
            }
        }

        #pragma unroll
        for (int i = 0; i < NPW; i++) {
            int n = base + i;
            if (n < N_NODES) {
                float4 ol = make_float4(al[i].x + bl4.x, al[i].y + bl4.y,
                                        al[i].z + bl4.z, al[i].w + bl4.w);
                float4 orr = make_float4(ar[i].x + br4.x, ar[i].y + br4.y,
                                         ar[i].z + br4.z, ar[i].w + br4.w);
                ((float4*)(g_xl + (size_t)n * DIM))[lane] = ol;
                ((float4*)(g_xr + (size_t)n * DIM))[lane] = orr;
            }
        }
    }
}

// ---------------------------------------------------------------------------
// Fused per-dst edge pass: softmax (max-free) + weighted gather + residual+LN.
// One warp per destination node. Lane L owns dims [4L, 4L+4); head = L>>3.
//
// alpha = exp(e)/sum(exp(e)) is exactly the reference softmax (max cancels;
// ref's +1e-16 is negligible since sum >= exp(max logit - max) = 1).
// ---------------------------------------------------------------------------
__global__ void fused_edge_kernel(const float* __restrict__ x,
                                  const float* __restrict__ att,
                                  const float* __restrict__ bias,
                                  const float* __restrict__ gamma,
                                  const float* __restrict__ beta,
                                  float* __restrict__ out) {
    const int lane = threadIdx.x & 31;
    const int warp = (blockIdx.x * blockDim.x + threadIdx.x) >> 5;
    const int nwarp = (gridDim.x * blockDim.x) >> 5;

    float4 at = ((const float4*)att)[lane];
    float4 bi = ((const float4*)bias)[lane];
    float4 ga = ((const float4*)gamma)[lane];
    float4 be = ((const float4*)beta)[lane];

    for (int d = warp; d < N_NODES; d += nwarp) {
        const int beg = g_off[d];
        const int deg = g_deg[d];
        float4 xr4 = ((const float4*)(g_xr + (size_t)d * DIM))[lane];

        float4 acc = make_float4(0.f, 0.f, 0.f, 0.f);
        float den = 0.f;

        for (int base = 0; base < deg; base += 32) {
            int cnt = min(32, deg - base);
            int my_src = (lane < cnt) ? g_csr_src[beg + base + lane] : 0;
            for (int j = 0; j < cnt; j++) {
                int s = __shfl_sync(0xffffffffu, my_src, j);
                float4 a = ((const float4*)(g_xl + (size_t)s * DIM))[lane];
                float vx = a.x + xr4.x; vx = vx > 0.f ? vx : NEG_SLOPE * vx;
                float vy = a.y + xr4.y; vy = vy > 0.f ? vy : NEG_SLOPE * vy;
                float vz = a.z + xr4.z; vz = vz > 0.f ? vz : NEG_SLOPE * vz;
                float vw = a.w + xr4.w; vw = vw > 0.f ? vw : NEG_SLOPE * vw;
                float p = vx * at.x + vy * at.y + vz * at.z + vw * at.w;
                // butterfly reduce within each 8-lane head group (all lanes get sum)
                p += __shfl_xor_sync(0xffffffffu, p, 4);
                p += __shfl_xor_sync(0xffffffffu, p, 2);
                p += __shfl_xor_sync(0xffffffffu, p, 1);
                float w = __expf(p);
                den += w;
                acc.x += w * a.x;
                acc.y += w * a.y;
                acc.z += w * a.z;
                acc.w += w * a.w;
            }
        }

        float inv = (den > 0.f) ? __frcp_rn(den) : 0.f;

        float4 xv = ((const float4*)(x + (size_t)d * DIM))[lane];
        float4 o;
        o.x = acc.x * inv + bi.x + xv.x;
        o.y = acc.y * inv + bi.y + xv.y;
        o.z = acc.z * inv + bi.z + xv.z;
        o.w = acc.w * inv + bi.w + xv.w;

        float s = o.x + o.y + o.z + o.w;
        #pragma unroll
        for (int off = 16; off > 0; off >>= 1)
            s += __shfl_xor_sync(0xffffffffu, s, off);
        float mu = s * (1.0f / DIM);

        float dx = o.x - mu, dy = o.y - mu, dz = o.z - mu, dw = o.w - mu;
        float q = dx * dx + dy * dy + dz * dz + dw * dw;
        #pragma unroll
        for (int off = 16; off > 0; off >>= 1)
            q += __shfl_xor_sync(0xffffffffu, q, off);
        float rs = rsqrtf(q * (1.0f / DIM) + LN_EPS);

        float4 r;
        r.x = dx * rs * ga.x + be.x;
        r.y = dy * rs * ga.y + be.y;
        r.z = dz * rs * ga.z + be.z;
        r.w = dw * rs * ga.w + be.w;
        ((float4*)(out + (size_t)d * DIM))[lane] = r;
    }
}

extern "C" void kernel_launch(void* const* d_in, const int* in_sizes, int n_in,
                              void* d_out, int out_size) {
    const float* x     = (const float*)d_in[0];
    const void*  ei    = d_in[1];
    const float* Wl    = (const float*)d_in[2];
    const float* bl    = (const float*)d_in[3];
    const float* Wr    = (const float*)d_in[4];
    const float* br    = (const float*)d_in[5];
    const float* att   = (const float*)d_in[6];
    const float* bias  = (const float*)d_in[7];
    const float* gamma = (const float*)d_in[8];
    const float* beta  = (const float*)d_in[9];
    float*       out   = (float*)d_out;

    sniff_kernel<<<1, 1>>>(ei);
    zero_deg_kernel<<<N_SCAN_BLKS, SCAN_BLK>>>();
    hist_kernel<<<1024, 256>>>(ei);
    scan1_kernel<<<N_SCAN_BLKS, SCAN_BLK>>>();
    scan2_kernel<<<1, SCAN_BLK>>>();
    scan3_kernel<<<N_SCAN_BLKS, SCAN_BLK>>>();
    fill_kernel<<<1024, 256>>>(ei);

    gemm_kernel<<<782, 256>>>(x, Wl, bl, Wr, br);

    // one warp per dst node: 50000 warps = 6250 blocks x 8 warps
    fused_edge_kernel<<<6250, 256>>>(x, att, bias, gamma, beta, out);
}

// round 4
// speedup vs baseline: 1.1444x; 1.0805x over previous
#include <cuda_runtime.h>

#define N_NODES 50000
#define N_EDGES 800000
#define DIM 128
#define HEADS 4
#define NEG_SLOPE 0.2f
#define LN_EPS 1e-5f

// Scratch (device globals: no allocation allowed in kernel_launch)
__device__ __align__(16) float g_xl[N_NODES * DIM];   // 25.6 MB
__device__ __align__(16) float g_xr[N_NODES * DIM];   // 25.6 MB
__device__ int g_deg[N_NODES];
__device__ int g_off[N_NODES];
__device__ int g_cursor[N_NODES];
__device__ int g_csr_src[N_EDGES];
__device__ int g_is64;

__device__ __forceinline__ int load_idx(const void* raw, int pos, int is64) {
    return is64 ? (int)((const long long*)raw)[pos] : ((const int*)raw)[pos];
}

// ---------------------------------------------------------------------------
// GEMM: xl = x@W_l + b_l ; xr = x@W_r + b_r. Warp computes 8 nodes.
// (launch index 0)
// ---------------------------------------------------------------------------
__global__ void gemm_kernel(const float* __restrict__ x,
                            const float* __restrict__ Wl, const float* __restrict__ bl,
                            const float* __restrict__ Wr, const float* __restrict__ br) {
    const int lane = threadIdx.x & 31;
    const int warp = (blockIdx.x * blockDim.x + threadIdx.x) >> 5;
    const int nwarp = (gridDim.x * blockDim.x) >> 5;
    const int NPW = 8;

    float4 bl4 = ((const float4*)bl)[lane];
    float4 br4 = ((const float4*)br)[lane];

    for (int base = warp * NPW; base < N_NODES; base += nwarp * NPW) {
        float4 xv[NPW];
        #pragma unroll
        for (int i = 0; i < NPW; i++) {
            int n = base + i;
            xv[i] = (n < N_NODES) ? ((const float4*)(x + (size_t)n * DIM))[lane]
                                  : make_float4(0.f, 0.f, 0.f, 0.f);
        }
        float4 al[NPW], ar[NPW];
        #pragma unroll
        for (int i = 0; i < NPW; i++) {
            al[i] = make_float4(0.f, 0.f, 0.f, 0.f);
            ar[i] = make_float4(0.f, 0.f, 0.f, 0.f);
        }

        #pragma unroll
        for (int k4 = 0; k4 < DIM / 4; k4++) {
            #pragma unroll
            for (int c = 0; c < 4; c++) {
                const int k = k4 * 4 + c;
                float4 wl = ((const float4*)(Wl + (size_t)k * DIM))[lane];
                float4 wr = ((const float4*)(Wr + (size_t)k * DIM))[lane];
                #pragma unroll
                for (int i = 0; i < NPW; i++) {
                    float comp = (c == 0) ? xv[i].x : (c == 1) ? xv[i].y
                               : (c == 2) ? xv[i].z : xv[i].w;
                    float xk = __shfl_sync(0xffffffffu, comp, k4);
                    al[i].x += xk * wl.x; al[i].y += xk * wl.y;
                    al[i].z += xk * wl.z; al[i].w += xk * wl.w;
                    ar[i].x += xk * wr.x; ar[i].y += xk * wr.y;
                    ar[i].z += xk * wr.z; ar[i].w += xk * wr.w;
                }
            }
        }

        #pragma unroll
        for (int i = 0; i < NPW; i++) {
            int n = base + i;
            if (n < N_NODES) {
                float4 ol = make_float4(al[i].x + bl4.x, al[i].y + bl4.y,
                                        al[i].z + bl4.z, al[i].w + bl4.w);
                float4 orr = make_float4(ar[i].x + br4.x, ar[i].y + br4.y,
                                         ar[i].z + br4.z, ar[i].w + br4.w);
                ((float4*)(g_xl + (size_t)n * DIM))[lane] = ol;
                ((float4*)(g_xr + (size_t)n * DIM))[lane] = orr;
            }
        }
    }
}

// ---------------------------------------------------------------------------
// prep (launch 1): dtype sniff + zero degree array.
// int32 data viewed as int64 combines index pairs into values >= 2^32
// (out of [0, N_NODES)) with overwhelming probability over 16 samples.
// ---------------------------------------------------------------------------
__global__ void prep_kernel(const void* __restrict__ ei_raw) {
    int i = blockIdx.x * blockDim.x + threadIdx.x;
    if (i == 0) {
        const long long* e64 = (const long long*)ei_raw;
        int ok = 1;
        #pragma unroll
        for (int j = 0; j < 16; j++) {
            long long v = e64[j];
            if (v < 0 || v >= N_NODES) ok = 0;
        }
        g_is64 = ok;
    }
    int stride = gridDim.x * blockDim.x;
    for (int j = i; j < N_NODES; j += stride) g_deg[j] = 0;
}

// launch 2: degree histogram
__global__ void hist_kernel(const void* __restrict__ ei_raw) {
    int is64 = g_is64;
    int i = blockIdx.x * blockDim.x + threadIdx.x;
    int stride = gridDim.x * blockDim.x;
    for (int e = i; e < N_EDGES; e += stride) {
        int d = load_idx(ei_raw, N_EDGES + e, is64);
        atomicAdd(&g_deg[d], 1);
    }
}

// ---------------------------------------------------------------------------
// launch 3: single-block exclusive scan of g_deg -> g_off, g_cursor.
// 1024 threads, each owns a contiguous chunk of ~49 nodes.
// ---------------------------------------------------------------------------
__global__ void scan_kernel() {
    const int T = 1024;
    const int CH = (N_NODES + T - 1) / T;   // 49
    int t = threadIdx.x;
    int lane = t & 31, wid = t >> 5;
    int beg = t * CH;
    int end = min(beg + CH, N_NODES);

    int sum = 0;
    for (int i = beg; i < end; i++) sum += g_deg[i];

    // inclusive warp scan of per-thread sums
    int v = sum;
    #pragma unroll
    for (int o = 1; o < 32; o <<= 1) {
        int u = __shfl_up_sync(0xffffffffu, v, o);
        if (lane >= o) v += u;
    }
    __shared__ int wsum[32];
    if (lane == 31) wsum[wid] = v;
    __syncthreads();
    if (wid == 0) {
        int w = wsum[lane];
        #pragma unroll
        for (int o = 1; o < 32; o <<= 1) {
            int u = __shfl_up_sync(0xffffffffu, w, o);
            if (lane >= o) w += u;
        }
        wsum[lane] = w;
    }
    __syncthreads();
    int excl = v - sum + (wid > 0 ? wsum[wid - 1] : 0);

    int run = excl;
    for (int i = beg; i < end; i++) {
        g_off[i] = run;
        g_cursor[i] = run;
        run += g_deg[i];
    }
}

// launch 4: CSR fill
__global__ void fill_kernel(const void* __restrict__ ei_raw) {
    int is64 = g_is64;
    int i = blockIdx.x * blockDim.x + threadIdx.x;
    int stride = gridDim.x * blockDim.x;
    for (int e = i; e < N_EDGES; e += stride) {
        int s = load_idx(ei_raw, e, is64);
        int d = load_idx(ei_raw, N_EDGES + e, is64);
        int pos = atomicAdd(&g_cursor[d], 1);
        g_csr_src[pos] = s;
    }
}

// ---------------------------------------------------------------------------
// launch 5 (ncu -s 5 captures this): fused per-dst softmax-gather + LN.
// One warp per destination node; edge loop unrolled x4 with independent
// accumulator pairs to expose MLP=4 and pipeline the shfl reductions.
// ---------------------------------------------------------------------------
__device__ __forceinline__ float edge_logit(float4 a, float4 xr4, float4 at) {
    float vx = a.x + xr4.x; vx = vx > 0.f ? vx : NEG_SLOPE * vx;
    float vy = a.y + xr4.y; vy = vy > 0.f ? vy : NEG_SLOPE * vy;
    float vz = a.z + xr4.z; vz = vz > 0.f ? vz : NEG_SLOPE * vz;
    float vw = a.w + xr4.w; vw = vw > 0.f ? vw : NEG_SLOPE * vw;
    return vx * at.x + vy * at.y + vz * at.z + vw * at.w;
}

__global__ void fused_edge_kernel(const float* __restrict__ x,
                                  const float* __restrict__ att,
                                  const float* __restrict__ bias,
                                  const float* __restrict__ gamma,
                                  const float* __restrict__ beta,
                                  float* __restrict__ out) {
    const int lane = threadIdx.x & 31;
    const int warp = (blockIdx.x * blockDim.x + threadIdx.x) >> 5;
    const int nwarp = (gridDim.x * blockDim.x) >> 5;
    const unsigned FULL = 0xffffffffu;

    float4 at = ((const float4*)att)[lane];
    float4 bi = ((const float4*)bias)[lane];
    float4 ga = ((const float4*)gamma)[lane];
    float4 be = ((const float4*)beta)[lane];

    for (int d = warp; d < N_NODES; d += nwarp) {
        const int beg = g_off[d];
        const int deg = g_deg[d];
        float4 xr4 = ((const float4*)(g_xr + (size_t)d * DIM))[lane];

        float4 accA = make_float4(0.f, 0.f, 0.f, 0.f);
        float4 accB = make_float4(0.f, 0.f, 0.f, 0.f);
        float denA = 0.f, denB = 0.f;

        for (int base = 0; base < deg; base += 32) {
            int cnt = min(32, deg - base);
            int my_src = (lane < cnt) ? g_csr_src[beg + base + lane] : 0;

            int j = 0;
            for (; j + 4 <= cnt; j += 4) {
                int s0 = __shfl_sync(FULL, my_src, j + 0);
                int s1 = __shfl_sync(FULL, my_src, j + 1);
                int s2 = __shfl_sync(FULL, my_src, j + 2);
                int s3 = __shfl_sync(FULL, my_src, j + 3);
                float4 a0 = ((const float4*)(g_xl + (size_t)s0 * DIM))[lane];
                float4 a1 = ((const float4*)(g_xl + (size_t)s1 * DIM))[lane];
                float4 a2 = ((const float4*)(g_xl + (size_t)s2 * DIM))[lane];
                float4 a3 = ((const float4*)(g_xl + (size_t)s3 * DIM))[lane];

                float p0 = edge_logit(a0, xr4, at);
                float p1 = edge_logit(a1, xr4, at);
                float p2 = edge_logit(a2, xr4, at);
                float p3 = edge_logit(a3, xr4, at);
                #pragma unroll
                for (int off = 4; off > 0; off >>= 1) {
                    p0 += __shfl_xor_sync(FULL, p0, off);
                    p1 += __shfl_xor_sync(FULL, p1, off);
                    p2 += __shfl_xor_sync(FULL, p2, off);
                    p3 += __shfl_xor_sync(FULL, p3, off);
                }
                float w0 = __expf(p0), w1 = __expf(p1);
                float w2 = __expf(p2), w3 = __expf(p3);
                denA += w0 + w1;
                denB += w2 + w3;
                accA.x += w0 * a0.x + w1 * a1.x;
                accA.y += w0 * a0.y + w1 * a1.y;
                accA.z += w0 * a0.z + w1 * a1.z;
                accA.w += w0 * a0.w + w1 * a1.w;
                accB.x += w2 * a2.x + w3 * a3.x;
                accB.y += w2 * a2.y + w3 * a3.y;
                accB.z += w2 * a2.z + w3 * a3.z;
                accB.w += w2 * a2.w + w3 * a3.w;
            }
            for (; j < cnt; j++) {
                int s = __shfl_sync(FULL, my_src, j);
                float4 a = ((const float4*)(g_xl + (size_t)s * DIM))[lane];
                float p = edge_logit(a, xr4, at);
                #pragma unroll
                for (int off = 4; off > 0; off >>= 1)
                    p += __shfl_xor_sync(FULL, p, off);
                float w = __expf(p);
                denA += w;
                accA.x += w * a.x;
                accA.y += w * a.y;
                accA.z += w * a.z;
                accA.w += w * a.w;
            }
        }

        float den = denA + denB;
        float4 acc = make_float4(accA.x + accB.x, accA.y + accB.y,
                                 accA.z + accB.z, accA.w + accB.w);
        float inv = (den > 0.f) ? __frcp_rn(den) : 0.f;

        float4 xv = ((const float4*)(x + (size_t)d * DIM))[lane];
        float4 o;
        o.x = acc.x * inv + bi.x + xv.x;
        o.y = acc.y * inv + bi.y + xv.y;
        o.z = acc.z * inv + bi.z + xv.z;
        o.w = acc.w * inv + bi.w + xv.w;

        float s = o.x + o.y + o.z + o.w;
        #pragma unroll
        for (int off = 16; off > 0; off >>= 1)
            s += __shfl_xor_sync(FULL, s, off);
        float mu = s * (1.0f / DIM);

        float dx = o.x - mu, dy = o.y - mu, dz = o.z - mu, dw = o.w - mu;
        float q = dx * dx + dy * dy + dz * dz + dw * dw;
        #pragma unroll
        for (int off = 16; off > 0; off >>= 1)
            q += __shfl_xor_sync(FULL, q, off);
        float rs = rsqrtf(q * (1.0f / DIM) + LN_EPS);

        float4 r;
        r.x = dx * rs * ga.x + be.x;
        r.y = dy * rs * ga.y + be.y;
        r.z = dz * rs * ga.z + be.z;
        r.w = dw * rs * ga.w + be.w;
        ((float4*)(out + (size_t)d * DIM))[lane] = r;
    }
}

extern "C" void kernel_launch(void* const* d_in, const int* in_sizes, int n_in,
                              void* d_out, int out_size) {
    const float* x     = (const float*)d_in[0];
    const void*  ei    = d_in[1];
    const float* Wl    = (const float*)d_in[2];
    const float* bl    = (const float*)d_in[3];
    const float* Wr    = (const float*)d_in[4];
    const float* br    = (const float*)d_in[5];
    const float* att   = (const float*)d_in[6];
    const float* bias  = (const float*)d_in[7];
    const float* gamma = (const float*)d_in[8];
    const float* beta  = (const float*)d_in[9];
    float*       out   = (float*)d_out;

    gemm_kernel<<<782, 256>>>(x, Wl, bl, Wr, br);          // 0
    prep_kernel<<<256, 256>>>(ei);                          // 1
    hist_kernel<<<1024, 256>>>(ei);                         // 2
    scan_kernel<<<1, 1024>>>();                             // 3
    fill_kernel<<<1024, 256>>>(ei);                         // 4
    fused_edge_kernel<<<6250, 256>>>(x, att, bias, gamma, beta, out);  // 5
}

// round 5
// speedup vs baseline: 1.4971x; 1.3082x over previous
#include <cuda_runtime.h>

#define N_NODES 50000
#define N_EDGES 800000
#define DIM 128
#define HEADS 4
#define NEG_SLOPE 0.2f
#define LN_EPS 1e-5f

#define SCAN_BLK 256
#define N_SCAN_BLKS ((N_NODES + SCAN_BLK - 1) / SCAN_BLK)   // 196

// Scratch (device globals: no allocation allowed in kernel_launch)
__device__ __align__(16) float g_xl[N_NODES * DIM];   // 25.6 MB
__device__ __align__(16) float g_xr[N_NODES * DIM];   // 25.6 MB
__device__ int g_deg[N_NODES];
__device__ int g_off[N_NODES];
__device__ int g_cursor[N_NODES];
__device__ int g_bsum[N_SCAN_BLKS];
__device__ int g_csr_src[N_EDGES];
__device__ int g_is64;

__device__ __forceinline__ int load_idx(const void* raw, int pos, int is64) {
    return is64 ? (int)((const long long*)raw)[pos] : ((const int*)raw)[pos];
}

// ---------------------------------------------------------------------------
// launch 0: dtype sniff + zero degree array.
// int32 data viewed as int64 combines index pairs into values >= 2^32
// (out of [0, N_NODES)) with overwhelming probability over 16 samples.
// ---------------------------------------------------------------------------
__global__ void prep_kernel(const void* __restrict__ ei_raw) {
    int i = blockIdx.x * blockDim.x + threadIdx.x;
    if (i == 0) {
        const long long* e64 = (const long long*)ei_raw;
        int ok = 1;
        #pragma unroll
        for (int j = 0; j < 16; j++) {
            long long v = e64[j];
            if (v < 0 || v >= N_NODES) ok = 0;
        }
        g_is64 = ok;
    }
    int stride = gridDim.x * blockDim.x;
    for (int j = i; j < N_NODES; j += stride) g_deg[j] = 0;
}

// launch 1: degree histogram
__global__ void hist_kernel(const void* __restrict__ ei_raw) {
    int is64 = g_is64;
    int i = blockIdx.x * blockDim.x + threadIdx.x;
    int stride = gridDim.x * blockDim.x;
    for (int e = i; e < N_EDGES; e += stride) {
        int d = load_idx(ei_raw, N_EDGES + e, is64);
        atomicAdd(&g_deg[d], 1);
    }
}

// ---------------------------------------------------------------------------
// launch 2: per-block inclusive scan of deg chunk; block total to g_bsum.
// ---------------------------------------------------------------------------
__global__ void scan1_kernel() {
    __shared__ int sh[SCAN_BLK];
    int tid = threadIdx.x;
    int i = blockIdx.x * SCAN_BLK + tid;
    int v = (i < N_NODES) ? g_deg[i] : 0;
    sh[tid] = v;
    __syncthreads();
    #pragma unroll
    for (int o = 1; o < SCAN_BLK; o <<= 1) {
        int t = (tid >= o) ? sh[tid - o] : 0;
        __syncthreads();
        sh[tid] += t;
        __syncthreads();
    }
    if (i < N_NODES) g_off[i] = sh[tid];           // inclusive local
    if (tid == SCAN_BLK - 1) g_bsum[blockIdx.x] = sh[tid];
}

// ---------------------------------------------------------------------------
// launch 3: finalize offsets. Each block recomputes its own exclusive prefix
// of the block totals (<= 196 values) with a shared-mem reduction.
// ---------------------------------------------------------------------------
__global__ void scan3_kernel() {
    __shared__ int sh[SCAN_BLK];
    int tid = threadIdx.x;
    int bid = blockIdx.x;
    sh[tid] = (tid < bid) ? g_bsum[tid] : 0;        // bid <= 196 <= SCAN_BLK
    __syncthreads();
    #pragma unroll
    for (int o = SCAN_BLK / 2; o > 0; o >>= 1) {
        if (tid < o) sh[tid] += sh[tid + o];
        __syncthreads();
    }
    int prefix = sh[0];
    int i = bid * SCAN_BLK + tid;
    if (i < N_NODES) {
        int excl = g_off[i] - g_deg[i] + prefix;
        g_off[i] = excl;
        g_cursor[i] = excl;
    }
}

// launch 4: CSR fill
__global__ void fill_kernel(const void* __restrict__ ei_raw) {
    int is64 = g_is64;
    int i = blockIdx.x * blockDim.x + threadIdx.x;
    int stride = gridDim.x * blockDim.x;
    for (int e = i; e < N_EDGES; e += stride) {
        int s = load_idx(ei_raw, e, is64);
        int d = load_idx(ei_raw, N_EDGES + e, is64);
        int pos = atomicAdd(&g_cursor[d], 1);
        g_csr_src[pos] = s;
    }
}

// ---------------------------------------------------------------------------
// launch 5 (ncu -s 5 profiles this): GEMM xl = x@W_l + b_l ; xr = x@W_r + b_r.
// Warp computes 8 nodes; lane L owns output columns [4L, 4L+4).
// ---------------------------------------------------------------------------
__global__ void gemm_kernel(const float* __restrict__ x,
                            const float* __restrict__ Wl, const float* __restrict__ bl,
                            const float* __restrict__ Wr, const float* __restrict__ br) {
    const int lane = threadIdx.x & 31;
    const int warp = (blockIdx.x * blockDim.x + threadIdx.x) >> 5;
    const int nwarp = (gridDim.x * blockDim.x) >> 5;
    const int NPW = 8;

    float4 bl4 = ((const float4*)bl)[lane];
    float4 br4 = ((const float4*)br)[lane];

    for (int base = warp * NPW; base < N_NODES; base += nwarp * NPW) {
        float4 xv[NPW];
        #pragma unroll
        for (int i = 0; i < NPW; i++) {
            int n = base + i;
            xv[i] = (n < N_NODES) ? ((const float4*)(x + (size_t)n * DIM))[lane]
                                  : make_float4(0.f, 0.f, 0.f, 0.f);
        }
        float4 al[NPW], ar[NPW];
        #pragma unroll
        for (int i = 0; i < NPW; i++) {
            al[i] = make_float4(0.f, 0.f, 0.f, 0.f);
            ar[i] = make_float4(0.f, 0.f, 0.f, 0.f);
        }

        #pragma unroll
        for (int k4 = 0; k4 < DIM / 4; k4++) {
            #pragma unroll
            for (int c = 0; c < 4; c++) {
                const int k = k4 * 4 + c;
                float4 wl = ((const float4*)(Wl + (size_t)k * DIM))[lane];
                float4 wr = ((const float4*)(Wr + (size_t)k * DIM))[lane];
                #pragma unroll
                for (int i = 0; i < NPW; i++) {
                    float comp = (c == 0) ? xv[i].x : (c == 1) ? xv[i].y
                               : (c == 2) ? xv[i].z : xv[i].w;
                    float xk = __shfl_sync(0xffffffffu, comp, k4);
                    al[i].x += xk * wl.x; al[i].y += xk * wl.y;
                    al[i].z += xk * wl.z; al[i].w += xk * wl.w;
                    ar[i].x += xk * wr.x; ar[i].y += xk * wr.y;
                    ar[i].z += xk * wr.z; ar[i].w += xk * wr.w;
                }
            }
        }

        #pragma unroll
        for (int i = 0; i < NPW; i++) {
            int n = base + i;
            if (n < N_NODES) {
                float4 ol = make_float4(al[i].x + bl4.x, al[i].y + bl4.y,
                                        al[i].z + bl4.z, al[i].w + bl4.w);
                float4 orr = make_float4(ar[i].x + br4.x, ar[i].y + br4.y,
                                         ar[i].z + br4.z, ar[i].w + br4.w);
                ((float4*)(g_xl + (size_t)n * DIM))[lane] = ol;
                ((float4*)(g_xr + (size_t)n * DIM))[lane] = orr;
            }
        }
    }
}

// ---------------------------------------------------------------------------
// launch 6: fused per-dst softmax-gather + residual + LN.
// One warp per destination node; edge loop unrolled x4 with independent
// accumulator pairs to expose MLP=4 and pipeline the shfl reductions.
// alpha = exp(e)/sum(exp(e)) equals the reference softmax (max cancels;
// ref's +1e-16 is negligible since the max term contributes exp(0)=1).
// ---------------------------------------------------------------------------
__device__ __forceinline__ float edge_logit(float4 a, float4 xr4, float4 at) {
    float vx = a.x + xr4.x; vx = vx > 0.f ? vx : NEG_SLOPE * vx;
    float vy = a.y + xr4.y; vy = vy > 0.f ? vy : NEG_SLOPE * vy;
    float vz = a.z + xr4.z; vz = vz > 0.f ? vz : NEG_SLOPE * vz;
    float vw = a.w + xr4.w; vw = vw > 0.f ? vw : NEG_SLOPE * vw;
    return vx * at.x + vy * at.y + vz * at.z + vw * at.w;
}

__global__ void fused_edge_kernel(const float* __restrict__ x,
                                  const float* __restrict__ att,
                                  const float* __restrict__ bias,
                                  const float* __restrict__ gamma,
                                  const float* __restrict__ beta,
                                  float* __restrict__ out) {
    const int lane = threadIdx.x & 31;
    const int warp = (blockIdx.x * blockDim.x + threadIdx.x) >> 5;
    const int nwarp = (gridDim.x * blockDim.x) >> 5;
    const unsigned FULL = 0xffffffffu;

    float4 at = ((const float4*)att)[lane];
    float4 bi = ((const float4*)bias)[lane];
    float4 ga = ((const float4*)gamma)[lane];
    float4 be = ((const float4*)beta)[lane];

    for (int d = warp; d < N_NODES; d += nwarp) {
        const int beg = g_off[d];
        const int deg = g_deg[d];
        float4 xr4 = ((const float4*)(g_xr + (size_t)d * DIM))[lane];

        float4 accA = make_float4(0.f, 0.f, 0.f, 0.f);
        float4 accB = make_float4(0.f, 0.f, 0.f, 0.f);
        float denA = 0.f, denB = 0.f;

        for (int base = 0; base < deg; base += 32) {
            int cnt = min(32, deg - base);
            int my_src = (lane < cnt) ? g_csr_src[beg + base + lane] : 0;

            int j = 0;
            for (; j + 4 <= cnt; j += 4) {
                int s0 = __shfl_sync(FULL, my_src, j + 0);
                int s1 = __shfl_sync(FULL, my_src, j + 1);
                int s2 = __shfl_sync(FULL, my_src, j + 2);
                int s3 = __shfl_sync(FULL, my_src, j + 3);
                float4 a0 = ((const float4*)(g_xl + (size_t)s0 * DIM))[lane];
                float4 a1 = ((const float4*)(g_xl + (size_t)s1 * DIM))[lane];
                float4 a2 = ((const float4*)(g_xl + (size_t)s2 * DIM))[lane];
                float4 a3 = ((const float4*)(g_xl + (size_t)s3 * DIM))[lane];

                float p0 = edge_logit(a0, xr4, at);
                float p1 = edge_logit(a1, xr4, at);
                float p2 = edge_logit(a2, xr4, at);
                float p3 = edge_logit(a3, xr4, at);
                #pragma unroll
                for (int off = 4; off > 0; off >>= 1) {
                    p0 += __shfl_xor_sync(FULL, p0, off);
                    p1 += __shfl_xor_sync(FULL, p1, off);
                    p2 += __shfl_xor_sync(FULL, p2, off);
                    p3 += __shfl_xor_sync(FULL, p3, off);
                }
                float w0 = __expf(p0), w1 = __expf(p1);
                float w2 = __expf(p2), w3 = __expf(p3);
                denA += w0 + w1;
                denB += w2 + w3;
                accA.x += w0 * a0.x + w1 * a1.x;
                accA.y += w0 * a0.y + w1 * a1.y;
                accA.z += w0 * a0.z + w1 * a1.z;
                accA.w += w0 * a0.w + w1 * a1.w;
                accB.x += w2 * a2.x + w3 * a3.x;
                accB.y += w2 * a2.y + w3 * a3.y;
                accB.z += w2 * a2.z + w3 * a3.z;
                accB.w += w2 * a2.w + w3 * a3.w;
            }
            for (; j < cnt; j++) {
                int s = __shfl_sync(FULL, my_src, j);
                float4 a = ((const float4*)(g_xl + (size_t)s * DIM))[lane];
                float p = edge_logit(a, xr4, at);
                #pragma unroll
                for (int off = 4; off > 0; off >>= 1)
                    p += __shfl_xor_sync(FULL, p, off);
                float w = __expf(p);
                denA += w;
                accA.x += w * a.x;
                accA.y += w * a.y;
                accA.z += w * a.z;
                accA.w += w * a.w;
            }
        }

        float den = denA + denB;
        float4 acc = make_float4(accA.x + accB.x, accA.y + accB.y,
                                 accA.z + accB.z, accA.w + accB.w);
        float inv = (den > 0.f) ? __frcp_rn(den) : 0.f;

        float4 xv = ((const float4*)(x + (size_t)d * DIM))[lane];
        float4 o;
        o.x = acc.x * inv + bi.x + xv.x;
        o.y = acc.y * inv + bi.y + xv.y;
        o.z = acc.z * inv + bi.z + xv.z;
        o.w = acc.w * inv + bi.w + xv.w;

        float s = o.x + o.y + o.z + o.w;
        #pragma unroll
        for (int off = 16; off > 0; off >>= 1)
            s += __shfl_xor_sync(FULL, s, off);
        float mu = s * (1.0f / DIM);

        float dx = o.x - mu, dy = o.y - mu, dz = o.z - mu, dw = o.w - mu;
        float q = dx * dx + dy * dy + dz * dz + dw * dw;
        #pragma unroll
        for (int off = 16; off > 0; off >>= 1)
            q += __shfl_xor_sync(FULL, q, off);
        float rs = rsqrtf(q * (1.0f / DIM) + LN_EPS);

        float4 r;
        r.x = dx * rs * ga.x + be.x;
        r.y = dy * rs * ga.y + be.y;
        r.z = dz * rs * ga.z + be.z;
        r.w = dw * rs * ga.w + be.w;
        ((float4*)(out + (size_t)d * DIM))[lane] = r;
    }
}

extern "C" void kernel_launch(void* const* d_in, const int* in_sizes, int n_in,
                              void* d_out, int out_size) {
    const float* x     = (const float*)d_in[0];
    const void*  ei    = d_in[1];
    const float* Wl    = (const float*)d_in[2];
    const float* bl    = (const float*)d_in[3];
    const float* Wr    = (const float*)d_in[4];
    const float* br    = (const float*)d_in[5];
    const float* att   = (const float*)d_in[6];
    const float* bias  = (const float*)d_in[7];
    const float* gamma = (const float*)d_in[8];
    const float* beta  = (const float*)d_in[9];
    float*       out   = (float*)d_out;

    prep_kernel<<<256, 256>>>(ei);                          // 0
    hist_kernel<<<1024, 256>>>(ei);                         // 1
    scan1_kernel<<<N_SCAN_BLKS, SCAN_BLK>>>();              // 2
    scan3_kernel<<<N_SCAN_BLKS, SCAN_BLK>>>();              // 3
    fill_kernel<<<1024, 256>>>(ei);                         // 4
    gemm_kernel<<<782, 256>>>(x, Wl, bl, Wr, br);           // 5  <- ncu -s 5
    fused_edge_kernel<<<6250, 256>>>(x, att, bias, gamma, beta, out);  // 6
}

// round 6
// speedup vs baseline: 1.6211x; 1.0829x over previous
#include <cuda_runtime.h>

#define N_NODES 50000
#define N_EDGES 800000
#define DIM 128
#define HEADS 4
#define NEG_SLOPE 0.2f
#define LN_EPS 1e-5f

#define SCAN_BLK 256
#define N_SCAN_BLKS ((N_NODES + SCAN_BLK - 1) / SCAN_BLK)   // 196

// Scratch (device globals: no allocation allowed in kernel_launch)
__device__ __align__(16) float g_xl[N_NODES * DIM];   // 25.6 MB
__device__ __align__(16) float g_xr[N_NODES * DIM];   // 25.6 MB
__device__ int g_deg[N_NODES];
__device__ int g_off[N_NODES];
__device__ int g_cursor[N_NODES];
__device__ int g_bsum[N_SCAN_BLKS];
__device__ int g_csr_src[N_EDGES];
__device__ int g_is64;

__device__ __forceinline__ int load_idx(const void* raw, int pos, int is64) {
    return is64 ? (int)((const long long*)raw)[pos] : ((const int*)raw)[pos];
}

// f32x2 packed helpers (sm_103a FFMA2 — only reachable via PTX)
__device__ __forceinline__ unsigned long long pack_dup(float v) {
    unsigned long long r;
    asm("mov.b64 %0, {%1, %1};" : "=l"(r) : "f"(v));
    return r;
}
__device__ __forceinline__ void fma2(unsigned long long& acc,
                                     unsigned long long a, unsigned long long b) {
    asm("fma.rn.f32x2 %0, %1, %2, %0;" : "+l"(acc) : "l"(a), "l"(b));
}
__device__ __forceinline__ float2 unpack2(unsigned long long v) {
    float lo, hi;
    asm("mov.b64 {%0, %1}, %2;" : "=f"(lo), "=f"(hi) : "l"(v));
    return make_float2(lo, hi);
}

// ---------------------------------------------------------------------------
// launch 0: dtype sniff + zero degree array.
// int32 data viewed as int64 combines index pairs into values >= 2^32
// (out of [0, N_NODES)) with overwhelming probability over 16 samples.
// ---------------------------------------------------------------------------
__global__ void prep_kernel(const void* __restrict__ ei_raw) {
    int i = blockIdx.x * blockDim.x + threadIdx.x;
    if (i == 0) {
        const long long* e64 = (const long long*)ei_raw;
        int ok = 1;
        #pragma unroll
        for (int j = 0; j < 16; j++) {
            long long v = e64[j];
            if (v < 0 || v >= N_NODES) ok = 0;
        }
        g_is64 = ok;
    }
    int stride = gridDim.x * blockDim.x;
    for (int j = i; j < N_NODES; j += stride) g_deg[j] = 0;
}

// launch 1: degree histogram
__global__ void hist_kernel(const void* __restrict__ ei_raw) {
    int is64 = g_is64;
    int i = blockIdx.x * blockDim.x + threadIdx.x;
    int stride = gridDim.x * blockDim.x;
    for (int e = i; e < N_EDGES; e += stride) {
        int d = load_idx(ei_raw, N_EDGES + e, is64);
        atomicAdd(&g_deg[d], 1);
    }
}

// launch 2: per-block inclusive scan of deg chunk; block total to g_bsum.
__global__ void scan1_kernel() {
    __shared__ int sh[SCAN_BLK];
    int tid = threadIdx.x;
    int i = blockIdx.x * SCAN_BLK + tid;
    int v = (i < N_NODES) ? g_deg[i] : 0;
    sh[tid] = v;
    __syncthreads();
    #pragma unroll
    for (int o = 1; o < SCAN_BLK; o <<= 1) {
        int t = (tid >= o) ? sh[tid - o] : 0;
        __syncthreads();
        sh[tid] += t;
        __syncthreads();
    }
    if (i < N_NODES) g_off[i] = sh[tid];           // inclusive local
    if (tid == SCAN_BLK - 1) g_bsum[blockIdx.x] = sh[tid];
}

// ---------------------------------------------------------------------------
// launch 3 (ncu captures this index): GEMM xl = x@W_l + b_l ; xr = x@W_r + b_r.
// Warp computes 8 nodes; lane L owns output columns [4L, 4L+4).
// Inner loop uses packed fma.rn.f32x2 (FFMA2): accumulators are column-pair
// packed u64; weight float4 loads reinterpret as 2 packed pairs for free.
// Bit-exact fp32 (each half is IEEE fp32 FMA).
// ---------------------------------------------------------------------------
__global__ void gemm_kernel(const float* __restrict__ x,
                            const float* __restrict__ Wl, const float* __restrict__ bl,
                            const float* __restrict__ Wr, const float* __restrict__ br) {
    const int lane = threadIdx.x & 31;
    const int warp = (blockIdx.x * blockDim.x + threadIdx.x) >> 5;
    const int nwarp = (gridDim.x * blockDim.x) >> 5;
    const int NPW = 8;

    float4 bl4 = ((const float4*)bl)[lane];
    float4 br4 = ((const float4*)br)[lane];

    for (int base = warp * NPW; base < N_NODES; base += nwarp * NPW) {
        float4 xv[NPW];
        #pragma unroll
        for (int i = 0; i < NPW; i++) {
            int n = base + i;
            xv[i] = (n < N_NODES) ? ((const float4*)(x + (size_t)n * DIM))[lane]
                                  : make_float4(0.f, 0.f, 0.f, 0.f);
        }
        // acc pairs: [i][0] = cols (4L,4L+1), [i][1] = cols (4L+2,4L+3)
        unsigned long long al2[NPW][2], ar2[NPW][2];
        #pragma unroll
        for (int i = 0; i < NPW; i++) {
            al2[i][0] = 0ull; al2[i][1] = 0ull;
            ar2[i][0] = 0ull; ar2[i][1] = 0ull;
        }

        #pragma unroll
        for (int k4 = 0; k4 < DIM / 4; k4++) {
            #pragma unroll
            for (int c = 0; c < 4; c++) {
                const int k = k4 * 4 + c;
                ulonglong2 wl2 = ((const ulonglong2*)(Wl + (size_t)k * DIM))[lane];
                ulonglong2 wr2 = ((const ulonglong2*)(Wr + (size_t)k * DIM))[lane];
                #pragma unroll
                for (int i = 0; i < NPW; i++) {
                    float comp = (c == 0) ? xv[i].x : (c == 1) ? xv[i].y
                               : (c == 2) ? xv[i].z : xv[i].w;
                    float xk = __shfl_sync(0xffffffffu, comp, k4);
                    unsigned long long xk2 = pack_dup(xk);
                    fma2(al2[i][0], wl2.x, xk2);
                    fma2(al2[i][1], wl2.y, xk2);
                    fma2(ar2[i][0], wr2.x, xk2);
                    fma2(ar2[i][1], wr2.y, xk2);
                }
            }
        }

        #pragma unroll
        for (int i = 0; i < NPW; i++) {
            int n = base + i;
            if (n < N_NODES) {
                float2 l01 = unpack2(al2[i][0]);
                float2 l23 = unpack2(al2[i][1]);
                float2 r01 = unpack2(ar2[i][0]);
                float2 r23 = unpack2(ar2[i][1]);
                float4 ol = make_float4(l01.x + bl4.x, l01.y + bl4.y,
                                        l23.x + bl4.z, l23.y + bl4.w);
                float4 orr = make_float4(r01.x + br4.x, r01.y + br4.y,
                                         r23.x + br4.z, r23.y + br4.w);
                ((float4*)(g_xl + (size_t)n * DIM))[lane] = ol;
                ((float4*)(g_xr + (size_t)n * DIM))[lane] = orr;
            }
        }
    }
}

// launch 4: finalize offsets. Each block recomputes its own exclusive prefix
// of the block totals (<= 196 values) with a shared-mem reduction.
__global__ void scan3_kernel() {
    __shared__ int sh[SCAN_BLK];
    int tid = threadIdx.x;
    int bid = blockIdx.x;
    sh[tid] = (tid < bid) ? g_bsum[tid] : 0;        // bid <= 196 <= SCAN_BLK
    __syncthreads();
    #pragma unroll
    for (int o = SCAN_BLK / 2; o > 0; o >>= 1) {
        if (tid < o) sh[tid] += sh[tid + o];
        __syncthreads();
    }
    int prefix = sh[0];
    int i = bid * SCAN_BLK + tid;
    if (i < N_NODES) {
        int excl = g_off[i] - g_deg[i] + prefix;
        g_off[i] = excl;
        g_cursor[i] = excl;
    }
}

// launch 5: CSR fill
__global__ void fill_kernel(const void* __restrict__ ei_raw) {
    int is64 = g_is64;
    int i = blockIdx.x * blockDim.x + threadIdx.x;
    int stride = gridDim.x * blockDim.x;
    for (int e = i; e < N_EDGES; e += stride) {
        int s = load_idx(ei_raw, e, is64);
        int d = load_idx(ei_raw, N_EDGES + e, is64);
        int pos = atomicAdd(&g_cursor[d], 1);
        g_csr_src[pos] = s;
    }
}

// ---------------------------------------------------------------------------
// launch 6: fused per-dst softmax-gather + residual + LN.
// One warp per destination node; edge loop unrolled x4 with independent
// accumulator pairs to expose MLP=4 and pipeline the shfl reductions.
// alpha = exp(e)/sum(exp(e)) equals the reference softmax (max cancels;
// ref's +1e-16 is negligible since the max term contributes exp(0)=1).
// ---------------------------------------------------------------------------
__device__ __forceinline__ float edge_logit(float4 a, float4 xr4, float4 at) {
    float vx = a.x + xr4.x; vx = vx > 0.f ? vx : NEG_SLOPE * vx;
    float vy = a.y + xr4.y; vy = vy > 0.f ? vy : NEG_SLOPE * vy;
    float vz = a.z + xr4.z; vz = vz > 0.f ? vz : NEG_SLOPE * vz;
    float vw = a.w + xr4.w; vw = vw > 0.f ? vw : NEG_SLOPE * vw;
    return vx * at.x + vy * at.y + vz * at.z + vw * at.w;
}

__global__ void fused_edge_kernel(const float* __restrict__ x,
                                  const float* __restrict__ att,
                                  const float* __restrict__ bias,
                                  const float* __restrict__ gamma,
                                  const float* __restrict__ beta,
                                  float* __restrict__ out) {
    const int lane = threadIdx.x & 31;
    const int warp = (blockIdx.x * blockDim.x + threadIdx.x) >> 5;
    const int nwarp = (gridDim.x * blockDim.x) >> 5;
    const unsigned FULL = 0xffffffffu;

    float4 at = ((const float4*)att)[lane];
    float4 bi = ((const float4*)bias)[lane];
    float4 ga = ((const float4*)gamma)[lane];
    float4 be = ((const float4*)beta)[lane];

    for (int d = warp; d < N_NODES; d += nwarp) {
        const int beg = g_off[d];
        const int deg = g_deg[d];
        float4 xr4 = ((const float4*)(g_xr + (size_t)d * DIM))[lane];

        float4 accA = make_float4(0.f, 0.f, 0.f, 0.f);
        float4 accB = make_float4(0.f, 0.f, 0.f, 0.f);
        float denA = 0.f, denB = 0.f;

        for (int base = 0; base < deg; base += 32) {
            int cnt = min(32, deg - base);
            int my_src = (lane < cnt) ? g_csr_src[beg + base + lane] : 0;

            int j = 0;
            for (; j + 4 <= cnt; j += 4) {
                int s0 = __shfl_sync(FULL, my_src, j + 0);
                int s1 = __shfl_sync(FULL, my_src, j + 1);
                int s2 = __shfl_sync(FULL, my_src, j + 2);
                int s3 = __shfl_sync(FULL, my_src, j + 3);
                float4 a0 = ((const float4*)(g_xl + (size_t)s0 * DIM))[lane];
                float4 a1 = ((const float4*)(g_xl + (size_t)s1 * DIM))[lane];
                float4 a2 = ((const float4*)(g_xl + (size_t)s2 * DIM))[lane];
                float4 a3 = ((const float4*)(g_xl + (size_t)s3 * DIM))[lane];

                float p0 = edge_logit(a0, xr4, at);
                float p1 = edge_logit(a1, xr4, at);
                float p2 = edge_logit(a2, xr4, at);
                float p3 = edge_logit(a3, xr4, at);
                #pragma unroll
                for (int off = 4; off > 0; off >>= 1) {
                    p0 += __shfl_xor_sync(FULL, p0, off);
                    p1 += __shfl_xor_sync(FULL, p1, off);
                    p2 += __shfl_xor_sync(FULL, p2, off);
                    p3 += __shfl_xor_sync(FULL, p3, off);
                }
                float w0 = __expf(p0), w1 = __expf(p1);
                float w2 = __expf(p2), w3 = __expf(p3);
                denA += w0 + w1;
                denB += w2 + w3;
                accA.x += w0 * a0.x + w1 * a1.x;
                accA.y += w0 * a0.y + w1 * a1.y;
                accA.z += w0 * a0.z + w1 * a1.z;
                accA.w += w0 * a0.w + w1 * a1.w;
                accB.x += w2 * a2.x + w3 * a3.x;
                accB.y += w2 * a2.y + w3 * a3.y;
                accB.z += w2 * a2.z + w3 * a3.z;
                accB.w += w2 * a2.w + w3 * a3.w;
            }
            for (; j < cnt; j++) {
                int s = __shfl_sync(FULL, my_src, j);
                float4 a = ((const float4*)(g_xl + (size_t)s * DIM))[lane];
                float p = edge_logit(a, xr4, at);
                #pragma unroll
                for (int off = 4; off > 0; off >>= 1)
                    p += __shfl_xor_sync(FULL, p, off);
                float w = __expf(p);
                denA += w;
                accA.x += w * a.x;
                accA.y += w * a.y;
                accA.z += w * a.z;
                accA.w += w * a.w;
            }
        }

        float den = denA + denB;
        float4 acc = make_float4(accA.x + accB.x, accA.y + accB.y,
                                 accA.z + accB.z, accA.w + accB.w);
        float inv = (den > 0.f) ? __frcp_rn(den) : 0.f;

        float4 xv = ((const float4*)(x + (size_t)d * DIM))[lane];
        float4 o;
        o.x = acc.x * inv + bi.x + xv.x;
        o.y = acc.y * inv + bi.y + xv.y;
        o.z = acc.z * inv + bi.z + xv.z;
        o.w = acc.w * inv + bi.w + xv.w;

        float s = o.x + o.y + o.z + o.w;
        #pragma unroll
        for (int off = 16; off > 0; off >>= 1)
            s += __shfl_xor_sync(FULL, s, off);
        float mu = s * (1.0f / DIM);

        float dx = o.x - mu, dy = o.y - mu, dz = o.z - mu, dw = o.w - mu;
        float q = dx * dx + dy * dy + dz * dz + dw * dw;
        #pragma unroll
        for (int off = 16; off > 0; off >>= 1)
            q += __shfl_xor_sync(FULL, q, off);
        float rs = rsqrtf(q * (1.0f / DIM) + LN_EPS);

        float4 r;
        r.x = dx * rs * ga.x + be.x;
        r.y = dy * rs * ga.y + be.y;
        r.z = dz * rs * ga.z + be.z;
        r.w = dw * rs * ga.w + be.w;
        ((float4*)(out + (size_t)d * DIM))[lane] = r;
    }
}

extern "C" void kernel_launch(void* const* d_in, const int* in_sizes, int n_in,
                              void* d_out, int out_size) {
    const float* x     = (const float*)d_in[0];
    const void*  ei    = d_in[1];
    const float* Wl    = (const float*)d_in[2];
    const float* bl    = (const float*)d_in[3];
    const float* Wr    = (const float*)d_in[4];
    const float* br    = (const float*)d_in[5];
    const float* att   = (const float*)d_in[6];
    const float* bias  = (const float*)d_in[7];
    const float* gamma = (const float*)d_in[8];
    const float* beta  = (const float*)d_in[9];
    float*       out   = (float*)d_out;

    prep_kernel<<<256, 256>>>(ei);                          // 0
    hist_kernel<<<1024, 256>>>(ei);                         // 1
    scan1_kernel<<<N_SCAN_BLKS, SCAN_BLK>>>();              // 2
    gemm_kernel<<<782, 256>>>(x, Wl, bl, Wr, br);           // 3  <- ncu captures
    scan3_kernel<<<N_SCAN_BLKS, SCAN_BLK>>>();              // 4
    fill_kernel<<<1024, 256>>>(ei);                         // 5
    fused_edge_kernel<<<6250, 256>>>(x, att, bias, gamma, beta, out);  // 6
}

// round 7
// speedup vs baseline: 1.6785x; 1.0354x over previous
#include <cuda_runtime.h>

#define N_NODES 50000
#define N_EDGES 800000
#define DIM 128
#define HEADS 4
#define NEG_SLOPE 0.2f
#define LN_EPS 1e-5f

#define SCAN_BLK 256
#define N_SCAN_BLKS ((N_NODES + SCAN_BLK - 1) / SCAN_BLK)   // 196

// Scratch (device globals: no allocation allowed in kernel_launch)
__device__ __align__(16) float g_xl[N_NODES * DIM];   // 25.6 MB
__device__ __align__(16) float g_xr[N_NODES * DIM];   // 25.6 MB
__device__ int g_deg[N_NODES];
__device__ int g_off[N_NODES];
__device__ int g_cursor[N_NODES];
__device__ int g_bsum[N_SCAN_BLKS];
__device__ int g_csr_src[N_EDGES];
__device__ int g_is64;

__device__ __forceinline__ int load_idx(const void* raw, int pos, int is64) {
    return is64 ? (int)((const long long*)raw)[pos] : ((const int*)raw)[pos];
}

// f32x2 packed helpers (sm_103a FFMA2 — only reachable via PTX)
__device__ __forceinline__ unsigned long long pack_dup(float v) {
    unsigned long long r;
    asm("mov.b64 %0, {%1, %1};" : "=l"(r) : "f"(v));
    return r;
}
__device__ __forceinline__ void fma2(unsigned long long& acc,
                                     unsigned long long a, unsigned long long b) {
    asm("fma.rn.f32x2 %0, %1, %2, %0;" : "+l"(acc) : "l"(a), "l"(b));
}
__device__ __forceinline__ float2 unpack2(unsigned long long v) {
    float lo, hi;
    asm("mov.b64 {%0, %1}, %2;" : "=f"(lo), "=f"(hi) : "l"(v));
    return make_float2(lo, hi);
}

// ---------------------------------------------------------------------------
// launch 0: dtype sniff + zero degree array.
// int32 data viewed as int64 combines index pairs into values >= 2^32
// (out of [0, N_NODES)) with overwhelming probability over 16 samples.
// ---------------------------------------------------------------------------
__global__ void prep_kernel(const void* __restrict__ ei_raw) {
    int i = blockIdx.x * blockDim.x + threadIdx.x;
    if (i == 0) {
        const long long* e64 = (const long long*)ei_raw;
        int ok = 1;
        #pragma unroll
        for (int j = 0; j < 16; j++) {
            long long v = e64[j];
            if (v < 0 || v >= N_NODES) ok = 0;
        }
        g_is64 = ok;
    }
    int stride = gridDim.x * blockDim.x;
    for (int j = i; j < N_NODES; j += stride) g_deg[j] = 0;
}

// launch 1: degree histogram
__global__ void hist_kernel(const void* __restrict__ ei_raw) {
    int is64 = g_is64;
    int i = blockIdx.x * blockDim.x + threadIdx.x;
    int stride = gridDim.x * blockDim.x;
    for (int e = i; e < N_EDGES; e += stride) {
        int d = load_idx(ei_raw, N_EDGES + e, is64);
        atomicAdd(&g_deg[d], 1);
    }
}

// launch 2: per-block inclusive scan of deg chunk; block total to g_bsum.
__global__ void scan1_kernel() {
    __shared__ int sh[SCAN_BLK];
    int tid = threadIdx.x;
    int i = blockIdx.x * SCAN_BLK + tid;
    int v = (i < N_NODES) ? g_deg[i] : 0;
    sh[tid] = v;
    __syncthreads();
    #pragma unroll
    for (int o = 1; o < SCAN_BLK; o <<= 1) {
        int t = (tid >= o) ? sh[tid - o] : 0;
        __syncthreads();
        sh[tid] += t;
        __syncthreads();
    }
    if (i < N_NODES) g_off[i] = sh[tid];           // inclusive local
    if (tid == SCAN_BLK - 1) g_bsum[blockIdx.x] = sh[tid];
}

// ---------------------------------------------------------------------------
// launch 3 (ncu captures this index): GEMM xl = x@W_l + b_l ; xr = x@W_r + b_r.
// Warp computes 4 nodes; lane L owns output columns [4L, 4L+4) of both
// matrices. Packed fma.rn.f32x2 inner loop (bit-exact fp32 per half).
// NPW=4 + launch_bounds(256,2) keeps regs <= 128 -> 2 blocks/SM so the
// W-load latency and shfl chains are hidden (R6 profile: 196 regs,
// occ 12.3%, issue 32.9% -- occupancy-bound).
// ---------------------------------------------------------------------------
__global__ void __launch_bounds__(256, 2)
gemm_kernel(const float* __restrict__ x,
            const float* __restrict__ Wl, const float* __restrict__ bl,
            const float* __restrict__ Wr, const float* __restrict__ br) {
    const int lane = threadIdx.x & 31;
    const int warp = (blockIdx.x * blockDim.x + threadIdx.x) >> 5;
    const int nwarp = (gridDim.x * blockDim.x) >> 5;
    const int NPW = 4;

    float4 bl4 = ((const float4*)bl)[lane];
    float4 br4 = ((const float4*)br)[lane];

    for (int base = warp * NPW; base < N_NODES; base += nwarp * NPW) {
        float4 xv[NPW];
        #pragma unroll
        for (int i = 0; i < NPW; i++) {
            int n = base + i;
            xv[i] = (n < N_NODES) ? ((const float4*)(x + (size_t)n * DIM))[lane]
                                  : make_float4(0.f, 0.f, 0.f, 0.f);
        }
        // acc pairs: [i][0] = cols (4L,4L+1), [i][1] = cols (4L+2,4L+3)
        unsigned long long al2[NPW][2], ar2[NPW][2];
        #pragma unroll
        for (int i = 0; i < NPW; i++) {
            al2[i][0] = 0ull; al2[i][1] = 0ull;
            ar2[i][0] = 0ull; ar2[i][1] = 0ull;
        }

        #pragma unroll
        for (int k4 = 0; k4 < DIM / 4; k4++) {
            #pragma unroll
            for (int c = 0; c < 4; c++) {
                const int k = k4 * 4 + c;
                ulonglong2 wl2 = ((const ulonglong2*)(Wl + (size_t)k * DIM))[lane];
                ulonglong2 wr2 = ((const ulonglong2*)(Wr + (size_t)k * DIM))[lane];
                #pragma unroll
                for (int i = 0; i < NPW; i++) {
                    float comp = (c == 0) ? xv[i].x : (c == 1) ? xv[i].y
                               : (c == 2) ? xv[i].z : xv[i].w;
                    float xk = __shfl_sync(0xffffffffu, comp, k4);
                    unsigned long long xk2 = pack_dup(xk);
                    fma2(al2[i][0], wl2.x, xk2);
                    fma2(al2[i][1], wl2.y, xk2);
                    fma2(ar2[i][0], wr2.x, xk2);
                    fma2(ar2[i][1], wr2.y, xk2);
                }
            }
        }

        #pragma unroll
        for (int i = 0; i < NPW; i++) {
            int n = base + i;
            if (n < N_NODES) {
                float2 l01 = unpack2(al2[i][0]);
                float2 l23 = unpack2(al2[i][1]);
                float2 r01 = unpack2(ar2[i][0]);
                float2 r23 = unpack2(ar2[i][1]);
                float4 ol = make_float4(l01.x + bl4.x, l01.y + bl4.y,
                                        l23.x + bl4.z, l23.y + bl4.w);
                float4 orr = make_float4(r01.x + br4.x, r01.y + br4.y,
                                         r23.x + br4.z, r23.y + br4.w);
                ((float4*)(g_xl + (size_t)n * DIM))[lane] = ol;
                ((float4*)(g_xr + (size_t)n * DIM))[lane] = orr;
            }
        }
    }
}

// launch 4: finalize offsets. Each block recomputes its own exclusive prefix
// of the block totals (<= 196 values) with a shared-mem reduction.
__global__ void scan3_kernel() {
    __shared__ int sh[SCAN_BLK];
    int tid = threadIdx.x;
    int bid = blockIdx.x;
    sh[tid] = (tid < bid) ? g_bsum[tid] : 0;        // bid <= 196 <= SCAN_BLK
    __syncthreads();
    #pragma unroll
    for (int o = SCAN_BLK / 2; o > 0; o >>= 1) {
        if (tid < o) sh[tid] += sh[tid + o];
        __syncthreads();
    }
    int prefix = sh[0];
    int i = bid * SCAN_BLK + tid;
    if (i < N_NODES) {
        int excl = g_off[i] - g_deg[i] + prefix;
        g_off[i] = excl;
        g_cursor[i] = excl;
    }
}

// launch 5: CSR fill
__global__ void fill_kernel(const void* __restrict__ ei_raw) {
    int is64 = g_is64;
    int i = blockIdx.x * blockDim.x + threadIdx.x;
    int stride = gridDim.x * blockDim.x;
    for (int e = i; e < N_EDGES; e += stride) {
        int s = load_idx(ei_raw, e, is64);
        int d = load_idx(ei_raw, N_EDGES + e, is64);
        int pos = atomicAdd(&g_cursor[d], 1);
        g_csr_src[pos] = s;
    }
}

// ---------------------------------------------------------------------------
// launch 6: fused per-dst softmax-gather + residual + LN.
// One warp per destination node; edge loop unrolled x4 with independent
// accumulator pairs to expose MLP=4 and pipeline the shfl reductions.
// alpha = exp(e)/sum(exp(e)) equals the reference softmax (max cancels;
// ref's +1e-16 is negligible since the max term contributes exp(0)=1).
// ---------------------------------------------------------------------------
__device__ __forceinline__ float edge_logit(float4 a, float4 xr4, float4 at) {
    float vx = a.x + xr4.x; vx = vx > 0.f ? vx : NEG_SLOPE * vx;
    float vy = a.y + xr4.y; vy = vy > 0.f ? vy : NEG_SLOPE * vy;
    float vz = a.z + xr4.z; vz = vz > 0.f ? vz : NEG_SLOPE * vz;
    float vw = a.w + xr4.w; vw = vw > 0.f ? vw : NEG_SLOPE * vw;
    return vx * at.x + vy * at.y + vz * at.z + vw * at.w;
}

__global__ void fused_edge_kernel(const float* __restrict__ x,
                                  const float* __restrict__ att,
                                  const float* __restrict__ bias,
                                  const float* __restrict__ gamma,
                                  const float* __restrict__ beta,
                                  float* __restrict__ out) {
    const int lane = threadIdx.x & 31;
    const int warp = (blockIdx.x * blockDim.x + threadIdx.x) >> 5;
    const int nwarp = (gridDim.x * blockDim.x) >> 5;
    const unsigned FULL = 0xffffffffu;

    float4 at = ((const float4*)att)[lane];
    float4 bi = ((const float4*)bias)[lane];
    float4 ga = ((const float4*)gamma)[lane];
    float4 be = ((const float4*)beta)[lane];

    for (int d = warp; d < N_NODES; d += nwarp) {
        const int beg = g_off[d];
        const int deg = g_deg[d];
        float4 xr4 = ((const float4*)(g_xr + (size_t)d * DIM))[lane];

        float4 accA = make_float4(0.f, 0.f, 0.f, 0.f);
        float4 accB = make_float4(0.f, 0.f, 0.f, 0.f);
        float denA = 0.f, denB = 0.f;

        for (int base = 0; base < deg; base += 32) {
            int cnt = min(32, deg - base);
            int my_src = (lane < cnt) ? g_csr_src[beg + base + lane] : 0;

            int j = 0;
            for (; j + 4 <= cnt; j += 4) {
                int s0 = __shfl_sync(FULL, my_src, j + 0);
                int s1 = __shfl_sync(FULL, my_src, j + 1);
                int s2 = __shfl_sync(FULL, my_src, j + 2);
                int s3 = __shfl_sync(FULL, my_src, j + 3);
                float4 a0 = ((const float4*)(g_xl + (size_t)s0 * DIM))[lane];
                float4 a1 = ((const float4*)(g_xl + (size_t)s1 * DIM))[lane];
                float4 a2 = ((const float4*)(g_xl + (size_t)s2 * DIM))[lane];
                float4 a3 = ((const float4*)(g_xl + (size_t)s3 * DIM))[lane];

                float p0 = edge_logit(a0, xr4, at);
                float p1 = edge_logit(a1, xr4, at);
                float p2 = edge_logit(a2, xr4, at);
                float p3 = edge_logit(a3, xr4, at);
                #pragma unroll
                for (int off = 4; off > 0; off >>= 1) {
                    p0 += __shfl_xor_sync(FULL, p0, off);
                    p1 += __shfl_xor_sync(FULL, p1, off);
                    p2 += __shfl_xor_sync(FULL, p2, off);
                    p3 += __shfl_xor_sync(FULL, p3, off);
                }
                float w0 = __expf(p0), w1 = __expf(p1);
                float w2 = __expf(p2), w3 = __expf(p3);
                denA += w0 + w1;
                denB += w2 + w3;
                accA.x += w0 * a0.x + w1 * a1.x;
                accA.y += w0 * a0.y + w1 * a1.y;
                accA.z += w0 * a0.z + w1 * a1.z;
                accA.w += w0 * a0.w + w1 * a1.w;
                accB.x += w2 * a2.x + w3 * a3.x;
                accB.y += w2 * a2.y + w3 * a3.y;
                accB.z += w2 * a2.z + w3 * a3.z;
                accB.w += w2 * a2.w + w3 * a3.w;
            }
            for (; j < cnt; j++) {
                int s = __shfl_sync(FULL, my_src, j);
                float4 a = ((const float4*)(g_xl + (size_t)s * DIM))[lane];
                float p = edge_logit(a, xr4, at);
                #pragma unroll
                for (int off = 4; off > 0; off >>= 1)
                    p += __shfl_xor_sync(FULL, p, off);
                float w = __expf(p);
                denA += w;
                accA.x += w * a.x;
                accA.y += w * a.y;
                accA.z += w * a.z;
                accA.w += w * a.w;
            }
        }

        float den = denA + denB;
        float4 acc = make_float4(accA.x + accB.x, accA.y + accB.y,
                                 accA.z + accB.z, accA.w + accB.w);
        float inv = (den > 0.f) ? __frcp_rn(den) : 0.f;

        float4 xv = ((const float4*)(x + (size_t)d * DIM))[lane];
        float4 o;
        o.x = acc.x * inv + bi.x + xv.x;
        o.y = acc.y * inv + bi.y + xv.y;
        o.z = acc.z * inv + bi.z + xv.z;
        o.w = acc.w * inv + bi.w + xv.w;

        float s = o.x + o.y + o.z + o.w;
        #pragma unroll
        for (int off = 16; off > 0; off >>= 1)
            s += __shfl_xor_sync(FULL, s, off);
        float mu = s * (1.0f / DIM);

        float dx = o.x - mu, dy = o.y - mu, dz = o.z - mu, dw = o.w - mu;
        float q = dx * dx + dy * dy + dz * dz + dw * dw;
        #pragma unroll
        for (int off = 16; off > 0; off >>= 1)
            q += __shfl_xor_sync(FULL, q, off);
        float rs = rsqrtf(q * (1.0f / DIM) + LN_EPS);

        float4 r;
        r.x = dx * rs * ga.x + be.x;
        r.y = dy * rs * ga.y + be.y;
        r.z = dz * rs * ga.z + be.z;
        r.w = dw * rs * ga.w + be.w;
        ((float4*)(out + (size_t)d * DIM))[lane] = r;
    }
}

extern "C" void kernel_launch(void* const* d_in, const int* in_sizes, int n_in,
                              void* d_out, int out_size) {
    const float* x     = (const float*)d_in[0];
    const void*  ei    = d_in[1];
    const float* Wl    = (const float*)d_in[2];
    const float* bl    = (const float*)d_in[3];
    const float* Wr    = (const float*)d_in[4];
    const float* br    = (const float*)d_in[5];
    const float* att   = (const float*)d_in[6];
    const float* bias  = (const float*)d_in[7];
    const float* gamma = (const float*)d_in[8];
    const float* beta  = (const float*)d_in[9];
    float*       out   = (float*)d_out;

    prep_kernel<<<256, 256>>>(ei);                          // 0
    hist_kernel<<<1024, 256>>>(ei);                         // 1
    scan1_kernel<<<N_SCAN_BLKS, SCAN_BLK>>>();              // 2
    // 50000 nodes / (4 nodes/warp * 8 warps/block) = 1563 blocks
    gemm_kernel<<<1563, 256>>>(x, Wl, bl, Wr, br);          // 3  <- ncu captures
    scan3_kernel<<<N_SCAN_BLKS, SCAN_BLK>>>();              // 4
    fill_kernel<<<1024, 256>>>(ei);                         // 5
    fused_edge_kernel<<<6250, 256>>>(x, att, bias, gamma, beta, out);  // 6
}